// round 15
// baseline (speedup 1.0000x reference)
#include <cuda_runtime.h>
#include <cstdint>

#define TSTEPS 16384
#define NBATCH 4
#define HDIM   128
#define NCLUS  4          // CTAs per cluster (one cluster per batch)
#define COLS   32         // h-columns per CTA
#define NTHR   384

// ---------------- device-global scratch (no runtime allocation) ------------
__device__ float g_hs[TSTEPS * NBATCH * HDIM];   // hidden states [t][b][128]
__device__ float g_M[384 * 4];                   // fused W_ih @ W_embed
__device__ float g_C[384];                       // fused bias (incl. b_ih)
__device__ float g_xq[TSTEPS * 20];              // packed x4 per b (16) + use_x flag (16)

// ---------------- helpers --------------------------------------------------
__device__ __forceinline__ void fma2(unsigned long long& d, unsigned long long a,
                                     unsigned long long b) {
    asm("fma.rn.f32x2 %0, %1, %2, %0;" : "+l"(d) : "l"(a), "l"(b));
}
__device__ __forceinline__ float f2sum(unsigned long long v) {
    float lo, hi;
    asm("mov.b64 {%0,%1}, %2;" : "=f"(lo), "=f"(hi) : "l"(v));
    return lo + hi;
}
__device__ __forceinline__ unsigned long long pack2(float lo, float hi) {
    unsigned long long v;
    asm("mov.b64 %0, {%1,%2};" : "=l"(v) : "f"(lo), "f"(hi));
    return v;
}
__device__ __forceinline__ uint32_t smem_u32(const void* p) {
    uint32_t a;
    asm("{ .reg .u64 t; cvta.to.shared.u64 t, %1; cvt.u32.u64 %0, t; }" : "=r"(a) : "l"(p));
    return a;
}
__device__ __forceinline__ float sigm(float x) {
    return __fdividef(1.0f, 1.0f + __expf(-x));
}
__device__ __forceinline__ float tanh_fast(float x) {
    float xc = fminf(fmaxf(x, -15.0f), 15.0f);
    float e = __expf(2.0f * xc);
    return __fdividef(e - 1.0f, e + 1.0f);
}
__device__ __forceinline__ void mbar_wait(uint32_t mb, uint32_t parity) {
    asm volatile(
        "{\n\t"
        ".reg .pred P;\n\t"
        "WL_%=:\n\t"
        "mbarrier.try_wait.parity.acquire.cluster.shared::cta.b64 P, [%0], %1, 0x989680;\n\t"
        "@P bra.uni WD_%=;\n\t"
        "bra.uni WL_%=;\n\t"
        "WD_%=:\n\t"
        "}"
        :: "r"(mb), "r"(parity) : "memory");
}

// ---------------- prep 1: fuse embed into the input-path matvec ------------
__global__ void prep_mc(const float* __restrict__ W_ih, const float* __restrict__ W_embed,
                        const float* __restrict__ b_embed, const float* __restrict__ b_ih) {
    int row = blockIdx.x * blockDim.x + threadIdx.x;
    if (row >= 384) return;
    float m0 = 0.f, m1 = 0.f, m2 = 0.f, m3 = 0.f, c = 0.f;
    for (int k = 0; k < HDIM; k++) {
        float w = W_ih[row * HDIM + k];
        m0 += w * W_embed[k * 4 + 0];
        m1 += w * W_embed[k * 4 + 1];
        m2 += w * W_embed[k * 4 + 2];
        m3 += w * W_embed[k * 4 + 3];
        c  += w * b_embed[k];
    }
    g_M[row * 4 + 0] = m0; g_M[row * 4 + 1] = m1;
    g_M[row * 4 + 2] = m2; g_M[row * 4 + 3] = m3;
    g_C[row] = c + b_ih[row];
}

// ---------------- prep 2: pack per-step inputs -----------------------------
// x = stack([px,py,vx,vy],0).transpose(0,2,1) -> [4, T, B]; model-batch s is
// the SIGNAL index: x[s, t, f] = sig_s[f, t].
__global__ void prep_xq(const float* __restrict__ px, const float* __restrict__ py,
                        const float* __restrict__ vx, const float* __restrict__ vy,
                        const int* __restrict__ mask, const int* __restrict__ cfn) {
    int t = blockIdx.x * blockDim.x + threadIdx.x;
    if (t >= TSTEPS) return;
    int ctx = cfn ? cfn[0] : 8;
    if (ctx < 1) ctx = 1;
    float ux = (t < ctx || mask[t] == 0) ? 1.f : 0.f;
    for (int f = 0; f < 4; f++) {
        g_xq[t * 20 + 0 * 4 + f] = px[f * TSTEPS + t];
        g_xq[t * 20 + 1 * 4 + f] = py[f * TSTEPS + t];
        g_xq[t * 20 + 2 * 4 + f] = vx[f * TSTEPS + t];
        g_xq[t * 20 + 3 * 4 + f] = vy[f * TSTEPS + t];
    }
    g_xq[t * 20 + 16] = ux;
}

// ---------------- sequential GRU: 4 clusters of 4 CTAs ---------------------
// Cluster = batch b = blockIdx.x/4. CTA rank owns h-cols [32r, 32r+32).
// 6 weight banks x 32 cols x 2 k-halves = 384 threads.
//   bank 0: Wsum(r)   feedback   bank 1: Wsum(z)   feedback
//   bank 2: Whh(r)    use_x      bank 3: Whh(z)    use_x
//   bank 4: Whh(n)    always     bank 5: Wih(n)    feedback
// tid: bank=tid/64; kh=(tid>>5)&1 (warp-uniform); col=tid&31.
// Each thread: 32 u64 weight regs (64 k-elems). kh-partials combined in SMEM.
// Gate warp (tid<32) computes gates + Mx, broadcasts h to 3 peers (DSMEM),
// lane0 arrives (release) on all peers' mbarriers (count=3, parity wait).
__global__ void __launch_bounds__(NTHR, 1) __cluster_dims__(NCLUS, 1, 1)
gru_seq(const float* __restrict__ W_hh, const float* __restrict__ W_ih,
        const float* __restrict__ b_hh, const float* __restrict__ b_ih) {
    __shared__ __align__(16) float SH[2][HDIM];   // double-buffered h
    __shared__ float SP[4][2][COLS];              // [slot][kh][col] partials
    __shared__ float SX[8][8];                    // x ring (8 steps)
    __shared__ __align__(8) unsigned long long s_mbar;

    int tid = threadIdx.x;
    uint32_t rank;
    asm("mov.u32 %0, %%cluster_ctarank;" : "=r"(rank));
    int b = blockIdx.x >> 2;

    // ---- init smem ----
    for (int i = tid; i < 2 * HDIM; i += NTHR) (&SH[0][0])[i] = 0.f;
    if (tid < 20) {                               // stage records t=0..3
        int rec = tid / 5, fi = tid % 5;
        SX[rec][fi] = g_xq[rec * 20 + (fi < 4 ? b * 4 + fi : 16)];
    }
    uint32_t mb = smem_u32(&s_mbar);
    if (tid == 0)
        asm volatile("mbarrier.init.shared.b64 [%0], %1;" :: "r"(mb), "r"(NCLUS - 1) : "memory");

    // ---- per-thread role & weights (32 u64) ----
    int bank = tid >> 6;
    int kh   = (tid >> 5) & 1;
    int col  = tid & 31;
    int G    = (int)rank * COLS + col;
    int part = (bank == 0 || bank == 2) ? 0 : (bank == 1 || bank == 3) ? 1 : 2;
    int grow = part * HDIM + G;
    bool wsum = (bank <= 1);
    bool wih  = (bank == 5);
    int q0 = (int)rank & 1, q1 = q0 ^ 1;
    bool localfirst = (kh == ((int)rank >> 1));

    unsigned long long w[32];
    {
        const float4* hh4 = (const float4*)(W_hh + grow * HDIM);
        const float4* ih4 = (const float4*)(W_ih + grow * HDIM);
#pragma unroll
        for (int i = 0; i < 16; i++) {
            int pc = (i < 8) ? (q0 * 8 + i) : (q1 * 8 + (i - 8));
            int kc = kh * 16 + pc;
            float4 a = wih ? ih4[kc] : hh4[kc];
            if (wsum) { float4 s = ih4[kc]; a.x += s.x; a.y += s.y; a.z += s.z; a.w += s.w; }
            w[2 * i]     = pack2(a.x, a.y);
            w[2 * i + 1] = pack2(a.z, a.w);
        }
    }
    float bias = 0.f;
    if (kh == 0) {
        float bh = b_hh[grow], bi = b_ih[grow];
        bias = wsum ? (bh + bi) : (wih ? bi : bh);
    }
    int spidx = (bank == 0 || bank == 2) ? 0 : (bank == 1 || bank == 3) ? 1
              : (bank == 4) ? 2 : 3;

    // ---- gate-warp extras (tid<32): M rows + peer addresses ----
    float mr0=0,mr1=0,mr2=0,mr3=0,cr=0, mz0=0,mz1=0,mz2=0,mz3=0,cz=0,
          mn0=0,mn1=0,mn2=0,mn3=0,cn=0;
    uint32_t psh0=0, psh1=0, psh2=0, pmb0=0, pmb1=0, pmb2=0;
    if (tid < 32) {
        int gr = G;                         // gate col = rank*32 + tid (col==tid)
        mr0=g_M[gr*4+0]; mr1=g_M[gr*4+1]; mr2=g_M[gr*4+2]; mr3=g_M[gr*4+3]; cr=g_C[gr];
        int gz = HDIM + gr;
        mz0=g_M[gz*4+0]; mz1=g_M[gz*4+1]; mz2=g_M[gz*4+2]; mz3=g_M[gz*4+3]; cz=g_C[gz];
        int gn = 2*HDIM + gr;
        mn0=g_M[gn*4+0]; mn1=g_M[gn*4+1]; mn2=g_M[gn*4+2]; mn3=g_M[gn*4+3]; cn=g_C[gn];
        uint32_t shb = smem_u32(&SH[0][0]);
        uint32_t p0 = (rank + 1) & 3, p1 = (rank + 2) & 3, p2 = (rank + 3) & 3;
        asm("mapa.shared::cluster.u32 %0, %1, %2;" : "=r"(psh0) : "r"(shb), "r"(p0));
        asm("mapa.shared::cluster.u32 %0, %1, %2;" : "=r"(psh1) : "r"(shb), "r"(p1));
        asm("mapa.shared::cluster.u32 %0, %1, %2;" : "=r"(psh2) : "r"(shb), "r"(p2));
        asm("mapa.shared::cluster.u32 %0, %1, %2;" : "=r"(pmb0) : "r"(mb), "r"(p0));
        asm("mapa.shared::cluster.u32 %0, %1, %2;" : "=r"(pmb1) : "r"(mb), "r"(p1));
        asm("mapa.shared::cluster.u32 %0, %1, %2;" : "=r"(pmb2) : "r"(mb), "r"(p2));
    }

    __syncthreads();
    asm volatile("barrier.cluster.arrive.aligned;" ::: "memory");
    asm volatile("barrier.cluster.wait.aligned;" ::: "memory");

    for (int t = 0; t < TSTEPS; t++) {
        int slot = t & 7, par = t & 1, np = par ^ 1;
        float ux = SX[slot][4];
        bool uxb = (ux != 0.f);
        bool active = uxb ? (bank >= 2 && bank <= 4) : (bank <= 1 || bank >= 4);

        // prefetch: every 4th step, 20 lanes load records t+4..t+7
        float pfv = 0.f; int prec = 0, pfi = 0; bool dopf = false;
        if (((t & 3) == 0) && tid < 20) {
            prec = t + 4 + tid / 5; pfi = tid % 5;
            if (prec < TSTEPS) {
                dopf = true;
                pfv = g_xq[prec * 20 + (pfi < 4 ? b * 4 + pfi : 16)];
            }
        }

        // ---- dot: local-quarter chunks before the wait (when possible) ----
        unsigned long long a0 = 0ull, a1 = 0ull;
        const ulonglong2* hp = (const ulonglong2*)(&SH[par][0]);
        if (active && localfirst) {
#pragma unroll
            for (int i = 0; i < 8; i++) {
                int kc = kh * 16 + q0 * 8 + i;
                ulonglong2 h2 = hp[kc];
                fma2(a0, w[2 * i], h2.x);
                fma2(a1, w[2 * i + 1], h2.y);
            }
        }

        if (t > 0) mbar_wait(mb, (uint32_t)((t - 1) & 1));

        if (active) {
            if (localfirst) {
#pragma unroll
                for (int i = 8; i < 16; i++) {
                    int kc = kh * 16 + q1 * 8 + (i - 8);
                    ulonglong2 h2 = hp[kc];
                    fma2(a0, w[2 * i], h2.x);
                    fma2(a1, w[2 * i + 1], h2.y);
                }
            } else {
#pragma unroll
                for (int i = 0; i < 16; i++) {
                    int pc = (i < 8) ? (q0 * 8 + i) : (q1 * 8 + (i - 8));
                    int kc = kh * 16 + pc;
                    ulonglong2 h2 = hp[kc];
                    fma2(a0, w[2 * i], h2.x);
                    fma2(a1, w[2 * i + 1], h2.y);
                }
            }
            SP[spidx][kh][col] = f2sum(a0) + f2sum(a1) + bias;
        }
        __syncthreads();

        // ---- gate phase: warp 0, one h-column each ----
        if (tid < 32) {
            float pr = SP[0][0][tid] + SP[0][1][tid];
            float pz = SP[1][0][tid] + SP[1][1][tid];
            float ph = SP[2][0][tid] + SP[2][1][tid];
            float pn;
            if (uxb) {
                float x0 = SX[slot][0], x1 = SX[slot][1], x2 = SX[slot][2], x3 = SX[slot][3];
                pr += mr0*x0 + mr1*x1 + mr2*x2 + mr3*x3 + cr;
                pz += mz0*x0 + mz1*x1 + mz2*x2 + mz3*x3 + cz;
                pn  = mn0*x0 + mn1*x1 + mn2*x2 + mn3*x3 + cn;
            } else {
                pn = SP[3][0][tid] + SP[3][1][tid];
            }
            float rg = sigm(pr);
            float zg = sigm(pz);
            float ng = tanh_fast(pn + rg * ph);
            float hold = SH[par][G];
            float hn = (1.f - zg) * ng + zg * hold;

            SH[np][G] = hn;
            uint32_t off = (uint32_t)((np * HDIM + G) * 4);
            asm volatile("st.shared::cluster.f32 [%0], %1;" :: "r"(psh0 + off), "f"(hn));
            asm volatile("st.shared::cluster.f32 [%0], %1;" :: "r"(psh1 + off), "f"(hn));
            asm volatile("st.shared::cluster.f32 [%0], %1;" :: "r"(psh2 + off), "f"(hn));
            g_hs[(t * NBATCH + b) * HDIM + G] = hn;

            __syncwarp();
            if (tid == 0) {
                asm volatile("mbarrier.arrive.release.cluster.shared::cluster.b64 _, [%0];"
                             :: "r"(pmb0) : "memory");
                asm volatile("mbarrier.arrive.release.cluster.shared::cluster.b64 _, [%0];"
                             :: "r"(pmb1) : "memory");
                asm volatile("mbarrier.arrive.release.cluster.shared::cluster.b64 _, [%0];"
                             :: "r"(pmb2) : "memory");
            }
        }
        if (dopf) SX[prec & 7][pfi] = pfv;
        __syncthreads();
    }

    asm volatile("barrier.cluster.arrive.aligned;" ::: "memory");
    asm volatile("barrier.cluster.wait.aligned;" ::: "memory");
}

// ---------------- MLP head over all (t,b) rows -----------------------------
__global__ void __launch_bounds__(256, 1)
head_kernel(const float* __restrict__ W1, const float* __restrict__ b1,
            const float* __restrict__ W2, const float* __restrict__ b2,
            const float* __restrict__ W3, const float* __restrict__ b3,
            float* __restrict__ out) {
    extern __shared__ float s[];
    float* sW1 = s;                 // 64*128
    float* sW2 = sW1 + 64 * 128;    // 64*64
    float* sW3 = sW2 + 64 * 64;     // 2*64
    float* sb1 = sW3 + 128;
    float* sb2 = sb1 + 64;
    float* sb3 = sb2 + 64;
    int tid = threadIdx.x;
    for (int i = tid; i < 64 * 128; i += 256) sW1[i] = W1[i];
    for (int i = tid; i < 64 * 64;  i += 256) sW2[i] = W2[i];
    for (int i = tid; i < 128;      i += 256) sW3[i] = W3[i];
    if (tid < 64) { sb1[tid] = b1[tid]; sb2[tid] = b2[tid]; }
    if (tid < 2)  sb3[tid] = b3[tid];
    __syncthreads();

    int row = blockIdx.x * 256 + tid;       // row = t*4 + b
    float h[128];
    const float4* hp = (const float4*)(g_hs + row * HDIM);
#pragma unroll
    for (int i = 0; i < 32; i++) {
        float4 v = hp[i];
        h[i * 4] = v.x; h[i * 4 + 1] = v.y; h[i * 4 + 2] = v.z; h[i * 4 + 3] = v.w;
    }
    float y1[64];
    for (int o = 0; o < 64; o++) {
        float acc = sb1[o];
        const float4* wp = (const float4*)(sW1 + o * 128);
#pragma unroll
        for (int i = 0; i < 32; i++) {
            float4 w = wp[i];
            acc += w.x * h[i * 4] + w.y * h[i * 4 + 1] + w.z * h[i * 4 + 2] + w.w * h[i * 4 + 3];
        }
        y1[o] = acc > 0.f ? acc : expm1f(acc);
    }
    float y2[64];
    for (int o = 0; o < 64; o++) {
        float acc = sb2[o];
        const float4* wp = (const float4*)(sW2 + o * 64);
#pragma unroll
        for (int i = 0; i < 16; i++) {
            float4 w = wp[i];
            acc += w.x * y1[i * 4] + w.y * y1[i * 4 + 1] + w.z * y1[i * 4 + 2] + w.w * y1[i * 4 + 3];
        }
        y2[o] = acc > 0.f ? acc : expm1f(acc);
    }
    float o0 = sb3[0], o1 = sb3[1];
#pragma unroll
    for (int k = 0; k < 64; k++) {
        o0 += sW3[k] * y2[k];
        o1 += sW3[64 + k] * y2[k];
    }
    int t = row >> 2, bb = row & 3;
    out[bb * TSTEPS + t] = o0;
    out[NBATCH * TSTEPS + bb * TSTEPS + t] = o1;
}

// ---------------- launch ---------------------------------------------------
extern "C" void kernel_launch(void* const* d_in, const int* in_sizes, int n_in,
                              void* d_out, int out_size) {
    const float* pos_x   = (const float*)d_in[0];
    const float* pos_y   = (const float*)d_in[1];
    const float* v_x     = (const float*)d_in[2];
    const float* v_y     = (const float*)d_in[3];
    const float* W_embed = (const float*)d_in[4];
    const float* b_embed = (const float*)d_in[5];
    const float* W_ih    = (const float*)d_in[6];
    const float* W_hh    = (const float*)d_in[7];
    const float* b_ih    = (const float*)d_in[8];
    const float* b_hh    = (const float*)d_in[9];
    const float* W1      = (const float*)d_in[10];
    const float* b1      = (const float*)d_in[11];
    const float* W2      = (const float*)d_in[12];
    const float* b2      = (const float*)d_in[13];
    const float* W3      = (const float*)d_in[14];
    const float* b3      = (const float*)d_in[15];
    const int*   mask    = (const int*)d_in[16];
    const int*   cfn     = (n_in > 17) ? (const int*)d_in[17] : nullptr;
    float* out = (float*)d_out;

    const int head_smem = (64 * 128 + 64 * 64 + 128 + 64 + 64 + 2) * 4;
    cudaFuncSetAttribute(head_kernel, cudaFuncAttributeMaxDynamicSharedMemorySize, head_smem);

    prep_mc<<<3, 128>>>(W_ih, W_embed, b_embed, b_ih);
    prep_xq<<<(TSTEPS + 255) / 256, 256>>>(pos_x, pos_y, v_x, v_y, mask, cfn);
    gru_seq<<<NCLUS * NBATCH, NTHR>>>(W_hh, W_ih, b_hh, b_ih);
    head_kernel<<<(TSTEPS * NBATCH) / 256, 256, head_smem>>>(W1, b1, W2, b2, W3, b3, out);
}